// round 15
// baseline (speedup 1.0000x reference)
#include <cuda_runtime.h>

#define S     32
#define SP    34
#define VOX   (S*S*S)        // 32768
#define PZ    35             // overlapping z-pair blocks
#define XSTR4 (SP*PZ*8)      // 9520 (float4 units)
#define YSTR4 (PZ*8)         // 280

// x repacked: [x:34][y:34][z0:35][c:16][zslot:2]  (pair block = 128 B aligned)
__device__ __align__(128) float g_xp2[SP*SP*PZ*32];   // 5.18 MB

// dynamic shared layout (float4 units)
#define WS_BASE  0           // 1728: [t:27][q:8][cp:8]
#define PAR_A_F4 1728        // 1728: (g00,g01,g10,g11)   [t:27][i:64]
#define PAR_B_F4 3456        // 864:  float2 (wlo, idxbits) [t:27][i:64]
#define SMEM_F4  4320        // 69120 bytes -> 3 CTAs/SM

// ---------------------------------------------------------------------------
// Pre-pass: pad + transpose x into overlapping z-pair, channels-inner layout.
// ---------------------------------------------------------------------------
__global__ void pad_pairs_kernel(const float* __restrict__ x) {
    int g = blockIdx.x * 256 + threadIdx.x;
    if (g >= SP*SP*PZ*8) return;
    int q  = g & 7;            // channel pair {2q, 2q+1}
    int sp = g >> 3;           // pair block (x,y,z0), z0 fastest
    int z0 = sp % PZ;
    int t  = sp / PZ;
    int y  = t % SP;
    int xx = t / SP;
    bool inb_xy = (xx >= 1 && xx <= S && y >= 1 && y <= S);
    bool ib0 = inb_xy && (z0 >= 1 && z0 <= S);     // value at padded z = z0
    bool ib1 = inb_xy && (z0 <= S - 1);            // value at padded z = z0+1
    int base = (xx-1)*(S*S) + (y-1)*S;
    int c0 = 2*q, c1 = 2*q + 1;
    float4 v;
    v.x = ib0 ? x[c0*VOX + base + z0 - 1] : 0.f;
    v.y = ib1 ? x[c0*VOX + base + z0    ] : 0.f;
    v.z = ib0 ? x[c1*VOX + base + z0 - 1] : 0.f;
    v.w = ib1 ? x[c1*VOX + base + z0    ] : 0.f;
    ((float4*)g_xp2)[(size_t)sp * 8 + q] = v;
}

// ---------------------------------------------------------------------------
// Main kernel. CTA = 256 threads = 64 output voxels; each lane handles TWO
// voxels (v, v+32); each weight LDS.128 serves 8 voxels per warp.
// Compressed params (24 B / voxel-tap) -> 69.1 KB smem -> 3 CTAs/SM.
// ---------------------------------------------------------------------------
__global__ void __launch_bounds__(256)
deform_conv3d_kernel(const float* __restrict__ off,
                     const float* __restrict__ wgt,
                     float* __restrict__ out)
{
    extern __shared__ __align__(16) float4 sm4[];
    float2* parB = (float2*)(sm4 + PAR_B_F4);
    const int tid = threadIdx.x;
    const int vbase = blockIdx.x * 64;

    // ---- weights: sm4[t*64 + q*8 + cp] =
    //      (w[2q][ci0], w[2q+1][ci0], w[2q][ci1], w[2q+1][ci1]), ci0 = 2*cp
    for (int idx = tid; idx < 1728; idx += 256) {
        int t  = idx >> 6;
        int q  = (idx >> 3) & 7;
        int cp = idx & 7;
        int ci0 = 2*cp, co0 = 2*q;
        float4 w;
        w.x = wgt[ co0      * 432 +  ci0      * 27 + t];
        w.y = wgt[(co0 + 1) * 432 +  ci0      * 27 + t];
        w.z = wgt[ co0      * 432 + (ci0 + 1) * 27 + t];
        w.w = wgt[(co0 + 1) * 432 + (ci0 + 1) * 27 + t];
        sm4[WS_BASE + t*64 + q*8 + cp] = w;
    }

    // ---- phase 1: params for all 1728 (tap, voxel) pairs of this tile
    for (int pt = tid; pt < 1728; pt += 256) {
        int i   = pt & 63;
        int tix = pt >> 6;
        int v  = vbase + i;
        int oh = v >> 10, ow = (v >> 5) & 31, od = v & 31;
        int a  = tix / 9;
        int bb = (tix - 9*a) / 3;
        int cc = tix - 9*a - 3*bb;
        int aw    = a * 32 + ow;
        int w_src = aw / 3;
        int r1    = aw - 3*w_src;
        int u     = r1 * 32 + od;
        int d_src = u / 3;
        int j     = u - 3*d_src;
        int n     = 9*bb + 3*j + cc;
        int vsrc  = (oh * 32 + w_src) * 32 + d_src;

        float px = (float)(oh    + bb) + off[ n        * VOX + vsrc];
        float py = (float)(w_src + j ) + off[(n + 27) * VOX + vsrc];
        float pz = (float)(d_src + cc) + off[(n + 54) * VOX + vsrc];

        float fx = floorf(px), fy = floorf(py), fz = floorf(pz);
        int q0x = min(max((int)fx,     0), 33);
        int q1x = min(max((int)fx + 1, 0), 33);
        int q0y = min(max((int)fy,     0), 33);
        int q1y = min(max((int)fy + 1, 0), 33);
        int q0z = min(max((int)fz,     0), 33);
        int q1z = min(max((int)fz + 1, 0), 33);

        float pxm = (px < 1.f || px > 32.f) ? fx : px;
        float pym = (py < 1.f || py > 32.f) ? fy : py;
        float pzm = (pz < 1.f || pz > 32.f) ? fz : pz;
        pxm = fminf(fmaxf(pxm, 0.f), 33.f);
        pym = fminf(fmaxf(pym, 0.f), 33.f);
        pzm = fminf(fmaxf(pzm, 0.f), 33.f);

        float lx = 1.f + ((float)q0x - pxm);
        float hx = 1.f - ((float)q1x - pxm);
        float ly = 1.f + ((float)q0y - pym);
        float hy = 1.f - ((float)q1y - pym);
        float lz = 1.f + ((float)q0z - pzm);
        float hz = 1.f - ((float)q1z - pzm);

        // z collapse: encode as wlo = lz + hz (=2) ; else wlo = lz, whi = 1-wlo
        bool  zc  = (q1z == q0z);
        float wlo = zc ? (lz + hz) : lz;

        // packed index: bits[0:20) base, bit20 = dX flag, bit21 = dY flag
        int pk = (q0x * XSTR4 + q0y * YSTR4 + q0z * 8)
               | ((q1x - q0x) << 20) | ((q1y - q0y) << 21);

        sm4[PAR_A_F4 + pt] = make_float4(lx*ly, lx*hy, hx*ly, hx*hy);
        parB[pt] = make_float2(wlo, __int_as_float(pk));
    }
    __syncthreads();

    // ---- phase 2: each lane owns voxels (vbase+iv) and (vbase+iv+32)
    const int cpart = tid & 7;
    const int iv    = tid >> 3;          // 0..31
    const int vA    = vbase + iv;
    const int vB    = vA + 32;
    const float4* __restrict__ xp = (const float4*)g_xp2;

    float accA[16], accB[16];
#pragma unroll
    for (int k = 0; k < 16; k++) { accA[k] = 0.f; accB[k] = 0.f; }

#pragma unroll 1
    for (int t = 0; t < 27; t++) {
        // voxel A params + corners
        float4 paA = sm4[PAR_A_F4 + t*64 + iv];
        float2 pwA = parB[t*64 + iv];
        int pkA = __float_as_int(pwA.y);
        int IA  = (pkA & 0xFFFFF) + cpart;
        int dXA = (pkA & (1 << 20)) ? XSTR4 : 0;
        int dYA = (pkA & (1 << 21)) ? YSTR4 : 0;
        float wloA = pwA.x;
        float whiA = (wloA > 1.5f) ? 0.f : 1.f - wloA;
        float4 a00 = xp[IA];
        float4 a01 = xp[IA + dYA];
        float4 a10 = xp[IA + dXA];
        float4 a11 = xp[IA + dXA + dYA];

        // voxel B params + corners
        float4 paB = sm4[PAR_A_F4 + t*64 + iv + 32];
        float2 pwB = parB[t*64 + iv + 32];
        int pkB = __float_as_int(pwB.y);
        int IB  = (pkB & 0xFFFFF) + cpart;
        int dXB = (pkB & (1 << 20)) ? XSTR4 : 0;
        int dYB = (pkB & (1 << 21)) ? YSTR4 : 0;
        float wloB = pwB.x;
        float whiB = (wloB > 1.5f) ? 0.f : 1.f - wloB;
        float4 b00 = xp[IB];
        float4 b01 = xp[IB + dYB];
        float4 b10 = xp[IB + dXB];
        float4 b11 = xp[IB + dXB + dYB];

        // interp voxel A
        float tA00a = fmaf(whiA, a00.y, wloA * a00.x);
        float tA00b = fmaf(whiA, a00.w, wloA * a00.z);
        float tA01a = fmaf(whiA, a01.y, wloA * a01.x);
        float tA01b = fmaf(whiA, a01.w, wloA * a01.z);
        float tA10a = fmaf(whiA, a10.y, wloA * a10.x);
        float tA10b = fmaf(whiA, a10.w, wloA * a10.z);
        float tA11a = fmaf(whiA, a11.y, wloA * a11.x);
        float tA11b = fmaf(whiA, a11.w, wloA * a11.z);
        float sA0 = fmaf(paA.w, tA11a, fmaf(paA.z, tA10a, fmaf(paA.y, tA01a, paA.x * tA00a)));
        float sA1 = fmaf(paA.w, tA11b, fmaf(paA.z, tA10b, fmaf(paA.y, tA01b, paA.x * tA00b)));

        // interp voxel B
        float tB00a = fmaf(whiB, b00.y, wloB * b00.x);
        float tB00b = fmaf(whiB, b00.w, wloB * b00.z);
        float tB01a = fmaf(whiB, b01.y, wloB * b01.x);
        float tB01b = fmaf(whiB, b01.w, wloB * b01.z);
        float tB10a = fmaf(whiB, b10.y, wloB * b10.x);
        float tB10b = fmaf(whiB, b10.w, wloB * b10.z);
        float tB11a = fmaf(whiB, b11.y, wloB * b11.x);
        float tB11b = fmaf(whiB, b11.w, wloB * b11.z);
        float sB0 = fmaf(paB.w, tB11a, fmaf(paB.z, tB10a, fmaf(paB.y, tB01a, paB.x * tB00a)));
        float sB1 = fmaf(paB.w, tB11b, fmaf(paB.z, tB10b, fmaf(paB.y, tB01b, paB.x * tB00b)));

        // conv accumulate: one weight load serves both voxels
        const float4* wr = sm4 + WS_BASE + t*64 + cpart;
#pragma unroll
        for (int q = 0; q < 8; q++) {
            float4 wq = wr[q * 8];
            accA[2*q]     = fmaf(wq.x, sA0, fmaf(wq.z, sA1, accA[2*q]));
            accA[2*q + 1] = fmaf(wq.y, sA0, fmaf(wq.w, sA1, accA[2*q + 1]));
            accB[2*q]     = fmaf(wq.x, sB0, fmaf(wq.z, sB1, accB[2*q]));
            accB[2*q + 1] = fmaf(wq.y, sB0, fmaf(wq.w, sB1, accB[2*q + 1]));
        }
    }

    // ---- reduce partial ci sums across the 8 lanes of each voxel
#pragma unroll
    for (int co = 0; co < 16; co++) {
        accA[co] += __shfl_xor_sync(0xffffffffu, accA[co], 1);
        accA[co] += __shfl_xor_sync(0xffffffffu, accA[co], 2);
        accA[co] += __shfl_xor_sync(0xffffffffu, accA[co], 4);
        accB[co] += __shfl_xor_sync(0xffffffffu, accB[co], 1);
        accB[co] += __shfl_xor_sync(0xffffffffu, accB[co], 2);
        accB[co] += __shfl_xor_sync(0xffffffffu, accB[co], 4);
    }
    int co0 = 2 * cpart;
    out[ co0      * VOX + vA] = accA[co0];
    out[(co0 + 1) * VOX + vA] = accA[co0 + 1];
    out[ co0      * VOX + vB] = accB[co0];
    out[(co0 + 1) * VOX + vB] = accB[co0 + 1];
}

// ---------------------------------------------------------------------------
extern "C" void kernel_launch(void* const* d_in, const int* in_sizes, int n_in,
                              void* d_out, int out_size) {
    const float* x   = (const float*)d_in[0];   // [1,16,32,32,32]
    const float* off = (const float*)d_in[1];   // [1,81,32,32,32]
    const float* wgt = (const float*)d_in[2];   // [16,16,3,3,3]
    float* out = (float*)d_out;                 // [1,16,32,32,32]

    cudaFuncSetAttribute(deform_conv3d_kernel,
                         cudaFuncAttributeMaxDynamicSharedMemorySize,
                         SMEM_F4 * 16);

    pad_pairs_kernel<<<(SP*SP*PZ*8 + 255) / 256, 256>>>(x);
    deform_conv3d_kernel<<<VOX / 64, 256, SMEM_F4 * 16>>>(off, wgt, out);
}